// round 15
// baseline (speedup 1.0000x reference)
#include <cuda_runtime.h>
#include <cuda_bf16.h>
#include <cuda_fp16.h>
#include <cstdint>

#define NN 110
#define CC 4096
#define NPAD 128

#define BM 128
#define BKC 64          // fp32 k per chunk
#define PITCHA 72       // 16-bit elems per A smem row (small kernels only)
#define NTH 256

#define PS (NPAD * CC)  // partial buffer stride
#define KT_FULL (CC / 16)   // 256 ktiles per 4096-K operand

// -------------------- scratch (zero-initialized device globals) ------------
__device__ float g_h   [NPAD * CC];
__device__ float g_aggr[NPAD * CC];
__device__ float g_Mn  [NPAD * NPAD];
__device__ float g_Wlp [NPAD * NPAD];
__device__ float g_P   [4 * PS];
// fragment-packed fp16 A operands: 8 mtiles x 256 ktiles x 32 lanes x uint4
__device__ uint4 g_xf[8 * KT_FULL * 32];
__device__ uint4 g_hf[8 * KT_FULL * 32];
__device__ uint4 g_af[8 * KT_FULL * 32];

// -------------------- helpers ----------------------------------------------
__device__ __forceinline__ uint32_t smem_u32(const void* p) {
    uint32_t a;
    asm("{ .reg .u64 t; cvta.to.shared.u64 t, %1; cvt.u32.u64 %0, t; }"
        : "=r"(a) : "l"(p));
    return a;
}

// bf16 split (small fused kernels)
__device__ __forceinline__ void split2(float x0, float x1, uint32_t& hi, uint32_t& lo) {
    uint32_t h;
    asm("cvt.rn.bf16x2.f32 %0, %1, %2;" : "=r"(h) : "f"(x1), "f"(x0));
    float h0 = __uint_as_float(h << 16);
    float h1 = __uint_as_float(h & 0xFFFF0000u);
    float r0 = x0 - h0;
    float r1 = x1 - h1;
    asm("cvt.rn.bf16x2.f32 %0, %1, %2;" : "=r"(lo) : "f"(r1), "f"(r0));
    hi = h;
}

__device__ __forceinline__ uint32_t cvth2(float x0, float x1) {
    uint32_t h;
    asm("cvt.rn.f16x2.f32 %0, %1, %2;" : "=r"(h) : "f"(x1), "f"(x0));
    return h;
}

#define LDMX4(r, addr)                                                        \
    asm volatile("ldmatrix.sync.aligned.m8n8.x4.shared.b16 {%0,%1,%2,%3}, [%4];" \
        : "=r"((r)[0]), "=r"((r)[1]), "=r"((r)[2]), "=r"((r)[3]) : "r"(addr))

#define LDMX4T(r, addr)                                                       \
    asm volatile("ldmatrix.sync.aligned.m8n8.x4.trans.shared.b16 {%0,%1,%2,%3}, [%4];" \
        : "=r"((r)[0]), "=r"((r)[1]), "=r"((r)[2]), "=r"((r)[3]) : "r"(addr))

#define MMA_BF16(acc, a, b0, b1)                                              \
    asm volatile("mma.sync.aligned.m16n8k16.row.col.f32.bf16.bf16.f32 "       \
        "{%0,%1,%2,%3}, {%4,%5,%6,%7}, {%8,%9}, {%0,%1,%2,%3};"               \
        : "+f"((acc)[0]), "+f"((acc)[1]), "+f"((acc)[2]), "+f"((acc)[3])      \
        : "r"((a)[0]), "r"((a)[1]), "r"((a)[2]), "r"((a)[3]), "r"(b0), "r"(b1))

#define MMA_F16_U4(acc, av, b0, b1)                                           \
    asm volatile("mma.sync.aligned.m16n8k16.row.col.f32.f16.f16.f32 "         \
        "{%0,%1,%2,%3}, {%4,%5,%6,%7}, {%8,%9}, {%0,%1,%2,%3};"               \
        : "+f"((acc)[0]), "+f"((acc)[1]), "+f"((acc)[2]), "+f"((acc)[3])      \
        : "r"((av).x), "r"((av).y), "r"((av).z), "r"((av).w), "r"(b0), "r"(b1))

// ---------------------------------------------------------------------------
// Prep: Mn[j][i] = (adj[i][j]!=0)/max(deg_j,1); Wl padded to 128 (fp32).
// ---------------------------------------------------------------------------
__global__ void prep_kernel(const int* __restrict__ adj, const float* __restrict__ Wl) {
    const int j = blockIdx.x;
    const int i = threadIdx.x;
    __shared__ int sdeg[NPAD];
    int a = (i < NN && j < NN) ? (adj[i * NN + j] != 0) : 0;
    sdeg[i] = a;
    __syncthreads();
#pragma unroll
    for (int s = 64; s > 0; s >>= 1) {
        if (i < s) sdeg[i] += sdeg[i + s];
        __syncthreads();
    }
    const int deg = sdeg[0];
    const float inv = (j < NN) ? 1.0f / (float)(deg > 1 ? deg : 1) : 0.0f;
    g_Mn [j * NPAD + i] = a ? inv : 0.0f;
    g_Wlp[j * NPAD + i] = (i < NN && j < NN) ? Wl[j * NN + i] : 0.0f;
}

// ---------------------------------------------------------------------------
// packA: fp32 [rows x K] row-major -> fragment-packed fp16.
// Block (mtile, ktile): 32 lanes x uint4; lane l holds
//   r0=(row,k),(row,k+1)  r1=(row+8,k..)  r2=(row,k+8..)  r3=(row+8,k+8..)
// with row = mtile*16 + (l>>2), k = ktile*16 + (l&3)*2.
// ---------------------------------------------------------------------------
__global__ void packA(const float* __restrict__ src, int lds, int Mreal,
                      uint4* __restrict__ dst, int kt) {
    int idx = blockIdx.x * blockDim.x + threadIdx.x;
    if (idx >= 8 * kt * 32) return;
    int lane  = idx & 31;
    int blk   = idx >> 5;
    int ktile = blk % kt;
    int mtile = blk / kt;
    int row = mtile * 16 + (lane >> 2);
    int k   = ktile * 16 + (lane & 3) * 2;
    const float2 z2 = make_float2(0.f, 0.f);
    float2 v00 = (row     < Mreal) ? *(const float2*)(src + (size_t)row * lds + k)           : z2;
    float2 v10 = (row + 8 < Mreal) ? *(const float2*)(src + (size_t)(row + 8) * lds + k)     : z2;
    float2 v01 = (row     < Mreal) ? *(const float2*)(src + (size_t)row * lds + k + 8)       : z2;
    float2 v11 = (row + 8 < Mreal) ? *(const float2*)(src + (size_t)(row + 8) * lds + k + 8) : z2;
    uint4 o;
    o.x = cvth2(v00.x, v00.y);
    o.y = cvth2(v10.x, v10.y);
    o.z = cvth2(v01.x, v01.y);
    o.w = cvth2(v11.x, v11.y);
    dst[idx] = o;
}

// ===========================================================================
// tgemm: big GEMM, single fp16, A fragment-packed in gmem (no A smem path).
// CTA tile 128 x BNT, 256 thr, 8 warps (4m x 2n), warp tile 32 x (BNT/2).
// B fp32 -> cvt -> smem (double-buffered). Writes fp32 partials.
// ===========================================================================
template<int BNT>
__global__ __launch_bounds__(NTH, 1)
void tgemm(const uint4* __restrict__ AF1, int kt1,      // ktiles of operand 1
           const float* __restrict__ B1, int ldb1,
           const uint4* __restrict__ AF2, int kt2,
           const float* __restrict__ B2, int ldb2,
           int SPLITS,
           float* __restrict__ C, int ldc, int Mreal)
{
    constexpr int NTW = BNT / 16;
    constexpr int PITCHB = BNT + 8;
    constexpr int NBG = NTW / 2;
    constexpr int FB = BNT / 16;
    constexpr uint32_t BBYTES = (uint32_t)BKC * PITCHB * 2;  // 17408 @BNT=128
    constexpr uint32_t STAGE  = BBYTES;

    extern __shared__ __align__(16) char dsm[];
    const uint32_t sb = smem_u32(dsm);

    const int tid = threadIdx.x;
    const int wid = tid >> 5;
    const int lid = tid & 31;
    const int ms = wid & 3;
    const int ns = wid >> 2;
    const int n0 = blockIdx.x * BNT;
    const int slice = blockIdx.y;

    const int pair = slice / SPLITS;
    const int q    = slice % SPLITS;
    const uint4* AF = pair ? AF2 : AF1;
    const float* B = pair ? B2 : B1;
    const int ldb = pair ? ldb2 : ldb1;
    const int kt  = pair ? kt2 : kt1;
    const int ktslice = kt / SPLITS;
    const int ktbase  = q * ktslice;
    const int T = ktslice / 4;          // 4 ktiles per chunk

    // B loader: 64 k x BNT n; thread -> (k row, BNT/4 n)
    const int bkq = tid >> 2;
    const int bnq = (tid & 3) * (BNT / 4);

    float acc[2][NTW][4];
#pragma unroll
    for (int a = 0; a < 2; ++a)
#pragma unroll
        for (int b = 0; b < NTW; ++b)
#pragma unroll
            for (int c = 0; c < 4; ++c) acc[a][b][c] = 0.0f;

    const uint32_t boff =
        (((uint32_t)(lid & 15) * PITCHB) + (uint32_t)(ns * (BNT / 2) + (lid >> 4) * 8)) * 2u;

    // A-frag bases for this warp's 2 m-tiles (uint4 index)
    const uint4* afb0 = AF + ((size_t)(ms * 2 + 0) * kt) * 32 + lid;
    const uint4* afb1 = AF + ((size_t)(ms * 2 + 1) * kt) * 32 + lid;

    float4 fbr[FB];
    uint4 af[2][2];   // [ks&1][mt]

#define LOADGB(T_)                                                             \
    do {                                                                       \
        int k0_ = (ktbase + (T_) * 4) * 16;                                    \
        const float* p_ = B + (size_t)(k0_ + bkq) * ldb + n0 + bnq;            \
        _Pragma("unroll")                                                      \
        for (int j = 0; j < FB; ++j)                                           \
            fbr[j] = *(const float4*)(p_ + j * 4);                             \
    } while (0)

#define STSB(bufsel)                                                           \
    do {                                                                       \
        char* st = dsm + (bufsel) * STAGE;                                     \
        uint32_t o_ = ((uint32_t)bkq * PITCHB + (uint32_t)bnq) * 2u;           \
        _Pragma("unroll")                                                      \
        for (int j = 0; j < FB; j += 2) {                                      \
            uint4 hv;                                                          \
            hv.x = cvth2(fbr[j].x,     fbr[j].y);                              \
            hv.y = cvth2(fbr[j].z,     fbr[j].w);                              \
            hv.z = cvth2(fbr[j + 1].x, fbr[j + 1].y);                          \
            hv.w = cvth2(fbr[j + 1].z, fbr[j + 1].w);                          \
            *(uint4*)(st + o_ + j * 8) = hv;                                   \
        }                                                                      \
    } while (0)

    // prefetch A frags for (chunk, kstep) into af[buf]
#define PREFA(buf, T_, KS_)                                                    \
    do {                                                                       \
        int g_ = ktbase + (T_) * 4 + (KS_);                                    \
        af[buf][0] = afb0[(size_t)g_ * 32];                                    \
        af[buf][1] = afb1[(size_t)g_ * 32];                                    \
    } while (0)

    // ---- prologue ----
    LOADGB(0);
    STSB(0);
    if (T > 1) LOADGB(1);
    PREFA(0, 0, 0);
    __syncthreads();

    for (int t = 0; t < T; ++t) {
        const uint32_t base = sb + (uint32_t)(t & 1) * STAGE;
#pragma unroll
        for (int ks = 0; ks < 4; ++ks) {
            // prefetch next kstep's A frags (next chunk's ks=0 when ks==3)
            if (ks < 3) {
                PREFA((ks + 1) & 1, t, ks + 1);
            } else if (t + 1 < T) {
                PREFA(0, t + 1, 0);
            }
            const uint32_t kB = (uint32_t)ks * 16u * PITCHB * 2u;
            uint32_t bh[NBG][4];
#pragma unroll
            for (int gp = 0; gp < NBG; ++gp)
                LDMX4T(bh[gp], base + boff + gp * 32u + kB);
#pragma unroll
            for (int mt = 0; mt < 2; ++mt)
#pragma unroll
                for (int nt = 0; nt < NTW; ++nt) {
                    const int gp = nt >> 1, ix = (nt & 1) * 2;
                    MMA_F16_U4(acc[mt][nt], af[ks & 1][mt], bh[gp][ix], bh[gp][ix + 1]);
                }
        }
        if (t + 1 < T) STSB((t + 1) & 1);
        if (t + 2 < T) LOADGB(t + 2);
        __syncthreads();
    }
#undef LOADGB
#undef STSB
#undef PREFA

    const int g  = lid >> 2;
    const int tq = lid & 3;
    float* Pout = C + (size_t)slice * PS;
#pragma unroll
    for (int mt = 0; mt < 2; ++mt) {
#pragma unroll
        for (int nt = 0; nt < NTW; ++nt) {
            int col = n0 + ns * (BNT / 2) + nt * 8 + tq * 2;
#pragma unroll
            for (int half = 0; half < 2; ++half) {
                int m = ms * 32 + mt * 16 + g + half * 8;
                if (m >= Mreal) continue;
                *(float2*)&Pout[(size_t)m * ldc + col] =
                    make_float2(acc[mt][nt][half * 2 + 0], acc[mt][nt][half * 2 + 1]);
            }
        }
    }
}

// ===========================================================================
// tgemm32f: small fused GEMM (bf16 3-term, R12-proven). CTA tile 128x32.
//   B[k][n] = (brelu? relu : id)( sum_{s<4} P_s[k][n] + bcol[n] )
// ===========================================================================
#define BNT32 32
#define PITCHB32 (BNT32 + 8)
#define AH32 0u
#define AL32 ((uint32_t)BM * PITCHA * 2u)            // 18432
#define BH32 (2u * AL32)                             // 36864
#define BB32 ((uint32_t)BKC * PITCHB32 * 2u)         // 5120
#define BL32 (BH32 + BB32)
#define ST32 (BH32 + 2u * BB32)                      // 47104
#define DS32 (2u * ST32)                             // 94208

__global__ __launch_bounds__(NTH, 1)
void tgemm32f(const float* __restrict__ A1,
              const float* __restrict__ P,
              const float* __restrict__ bcol,
              int brelu,
              float* __restrict__ hout,
              const float* __restrict__ rowbias,
              float* __restrict__ C, int ldc, int Mreal)
{
    extern __shared__ __align__(16) char dsm[];
    const uint32_t sb = smem_u32(dsm);

    const int tid = threadIdx.x;
    const int wid = tid >> 5;
    const int lid = tid & 31;
    const int ms = wid & 3;
    const int ns = wid >> 2;
    const int n0 = blockIdx.x * BNT32;

    const int T = NPAD / BKC;   // 2

    const int alrow = tid >> 4;
    const int alc   = (tid & 15) * 4;
    const int bkq = tid >> 2;
    const int bnq = (tid & 3) * 8;

    float acc[2][2][4];
#pragma unroll
    for (int a = 0; a < 2; ++a)
#pragma unroll
        for (int b = 0; b < 2; ++b)
#pragma unroll
            for (int c = 0; c < 4; ++c) acc[a][b][c] = 0.0f;

    const uint32_t aoffH = AH32 +
        (((uint32_t)(ms * 32 + (lid & 15)) * PITCHA) + ((lid >> 4) & 1) * 8u) * 2u;
    const uint32_t boff = BH32 +
        (((uint32_t)(lid & 15) * PITCHB32) + (uint32_t)(ns * 16 + (lid >> 4) * 8)) * 2u;

    float4 fa[8];
    float4 fbr[2];
    const float4 f4z = make_float4(0.f, 0.f, 0.f, 0.f);

#define LOADG(T_)                                                              \
    do {                                                                       \
        int k0_ = (T_) * BKC;                                                  \
        _Pragma("unroll")                                                      \
        for (int p = 0; p < 8; ++p) {                                          \
            int m = p * 16 + alrow;                                            \
            fa[p] = (m < Mreal) ? *(const float4*)(A1 + (size_t)m * NPAD + k0_ + alc) : f4z; \
        }                                                                      \
        int krow = k0_ + bkq;                                                  \
        const float* pp = P + (size_t)krow * CC + n0 + bnq;                    \
        _Pragma("unroll")                                                      \
        for (int j = 0; j < 2; ++j) {                                          \
            float4 p0 = *(const float4*)(pp + j * 4);                          \
            float4 p1 = *(const float4*)(pp + PS + j * 4);                     \
            float4 p2 = *(const float4*)(pp + 2 * PS + j * 4);                 \
            float4 p3 = *(const float4*)(pp + 3 * PS + j * 4);                 \
            float4 bv = *(const float4*)(bcol + n0 + bnq + j * 4);             \
            float4 v;                                                          \
            v.x = (p0.x + p1.x) + (p2.x + p3.x) + bv.x;                        \
            v.y = (p0.y + p1.y) + (p2.y + p3.y) + bv.y;                        \
            v.z = (p0.z + p1.z) + (p2.z + p3.z) + bv.z;                        \
            v.w = (p0.w + p1.w) + (p2.w + p3.w) + bv.w;                        \
            if (brelu) {                                                       \
                v.x = fmaxf(v.x, 0.f); v.y = fmaxf(v.y, 0.f);                  \
                v.z = fmaxf(v.z, 0.f); v.w = fmaxf(v.w, 0.f);                  \
            }                                                                  \
            fbr[j] = v;                                                        \
        }                                                                      \
        if (hout != nullptr && krow < NN) {                                    \
            float* ho = hout + (size_t)krow * CC + n0 + bnq;                   \
            *(float4*)(ho)     = fbr[0];                                       \
            *(float4*)(ho + 4) = fbr[1];                                       \
        }                                                                      \
    } while (0)

#define STORE_STAGE(bufsel)                                                    \
    do {                                                                       \
        char* st = dsm + (bufsel) * ST32;                                      \
        _Pragma("unroll")                                                      \
        for (int p = 0; p < 8; ++p) {                                          \
            int row = p * 16 + alrow;                                          \
            uint32_t h0, l0, h1, l1;                                           \
            split2(fa[p].x, fa[p].y, h0, l0);                                  \
            split2(fa[p].z, fa[p].w, h1, l1);                                  \
            uint32_t off = ((uint32_t)row * PITCHA + (uint32_t)alc) * 2u;      \
            *(uint2*)(st + AH32 + off) = make_uint2(h0, h1);                   \
            *(uint2*)(st + AL32 + off) = make_uint2(l0, l1);                   \
        }                                                                      \
        {                                                                      \
            uint32_t o_ = ((uint32_t)bkq * PITCHB32 + (uint32_t)bnq) * 2u;     \
            uint4 hv, lv;                                                      \
            split2(fbr[0].x, fbr[0].y, hv.x, lv.x);                            \
            split2(fbr[0].z, fbr[0].w, hv.y, lv.y);                            \
            split2(fbr[1].x, fbr[1].y, hv.z, lv.z);                            \
            split2(fbr[1].z, fbr[1].w, hv.w, lv.w);                            \
            *(uint4*)(st + BH32 + o_) = hv;                                    \
            *(uint4*)(st + BL32 + o_) = lv;                                    \
        }                                                                      \
    } while (0)

    LOADG(0);
    STORE_STAGE(0);
    LOADG(1);
    __syncthreads();

    for (int t = 0; t < T; ++t) {
        const uint32_t base = sb + (uint32_t)(t & 1) * ST32;
#pragma unroll
        for (int ks = 0; ks < 4; ++ks) {
            const uint32_t kA = (uint32_t)ks * 32u;
            const uint32_t kB = (uint32_t)ks * 16u * PITCHB32 * 2u;
            uint32_t ah[2][4], al[2][4], bh[4], bl[4];
            LDMX4(ah[0], base + aoffH + kA);
            LDMX4(ah[1], base + aoffH + 16u * PITCHA * 2u + kA);
            LDMX4(al[0], base + aoffH + (AL32 - AH32) + kA);
            LDMX4(al[1], base + aoffH + (AL32 - AH32) + 16u * PITCHA * 2u + kA);
            LDMX4T(bh, base + boff + kB);
            LDMX4T(bl, base + boff + (BL32 - BH32) + kB);
#pragma unroll
            for (int mt = 0; mt < 2; ++mt)
#pragma unroll
                for (int nt = 0; nt < 2; ++nt) {
                    const int ix = nt * 2;
                    MMA_BF16(acc[mt][nt], ah[mt], bh[ix], bh[ix + 1]);
                    MMA_BF16(acc[mt][nt], ah[mt], bl[ix], bl[ix + 1]);
                    MMA_BF16(acc[mt][nt], al[mt], bh[ix], bh[ix + 1]);
                }
        }
        if (t + 1 < T) STORE_STAGE((t + 1) & 1);
        __syncthreads();
    }
#undef LOADG
#undef STORE_STAGE

    const int g  = lid >> 2;
    const int tq = lid & 3;
#pragma unroll
    for (int mt = 0; mt < 2; ++mt) {
#pragma unroll
        for (int nt = 0; nt < 2; ++nt) {
            int col = n0 + ns * 16 + nt * 8 + tq * 2;
#pragma unroll
            for (int half = 0; half < 2; ++half) {
                int m = ms * 32 + mt * 16 + g + half * 8;
                if (m >= Mreal) continue;
                float rb = (rowbias != nullptr) ? rowbias[m] : 0.0f;
                float vx = acc[mt][nt][half * 2 + 0] + rb;
                float vy = acc[mt][nt][half * 2 + 1] + rb;
                *(float2*)&C[(size_t)m * ldc + col] = make_float2(vx, vy);
            }
        }
    }
}

// ---------------------------------------------------------------------------
extern "C" void kernel_launch(void* const* d_in, const int* in_sizes, int n_in,
                              void* d_out, int out_size)
{
    const float* x   = (const float*)d_in[0];
    const int*   adj = (const int*)  d_in[1];
    const float* W2  = (const float*)d_in[2];
    const float* b2  = (const float*)d_in[3];
    const float* W1  = (const float*)d_in[4];
    const float* b1  = (const float*)d_in[5];
    const float* Wl  = (const float*)d_in[6];
    const float* bl  = (const float*)d_in[7];
    float* out = (float*)d_out;

    float *h, *aggr, *Mn, *Wlp, *P;
    uint4 *xf, *hf, *af;
    cudaGetSymbolAddress((void**)&h,    g_h);
    cudaGetSymbolAddress((void**)&aggr, g_aggr);
    cudaGetSymbolAddress((void**)&Mn,   g_Mn);
    cudaGetSymbolAddress((void**)&Wlp,  g_Wlp);
    cudaGetSymbolAddress((void**)&P,    g_P);
    cudaGetSymbolAddress((void**)&xf,   g_xf);
    cudaGetSymbolAddress((void**)&hf,   g_hf);
    cudaGetSymbolAddress((void**)&af,   g_af);

    // B-only double-buffered stage
    const int DS128 = 2 * (BKC * (128 + 8) * 2);   // 34816
    cudaFuncSetAttribute(tgemm<128>, cudaFuncAttributeMaxDynamicSharedMemorySize, DS128);
    cudaFuncSetAttribute(tgemm32f, cudaFuncAttributeMaxDynamicSharedMemorySize, DS32);

    dim3 b(NTH);
    dim3 gBig(CC / 128, 4);    // 32 x 4 slices = 128 CTAs
    dim3 gF  (CC / BNT32);     // 128 CTAs
    const int PACKN = 8 * KT_FULL * 32;            // 65536 threads per pack

    prep_kernel<<<NPAD, NPAD>>>(adj, Wl);
    packA<<<(PACKN + 255) / 256, 256>>>(x, CC, NN, xf, KT_FULL);

    // K1: P_s = xf @ W2 over 4 k-slices of 1024 (single fp16, frag A)
    tgemm<128><<<gBig, b, DS128>>>(xf, KT_FULL, W2, CC,
                                   nullptr, 0, nullptr, 0,
                                   /*SPLITS=*/4, P, CC, NN);

    // K2 (fused): B = h = sum P + b2 (materialized to g_h); aggr = Mn @ h
    tgemm32f<<<gF, b, DS32>>>(Mn, P, b2, /*brelu=*/0,
                              /*hout=*/h, /*rowbias=*/nullptr,
                              aggr, CC, NN);

    // pack h and aggr into fragment layout for K3
    packA<<<(PACKN + 255) / 256, 256>>>(h,    CC, NN, hf, KT_FULL);
    packA<<<(PACKN + 255) / 256, 256>>>(aggr, CC, NN, af, KT_FULL);

    // K3: P_s = (hf @ W1_top | af @ W1_bot), each pair split in 2
    tgemm<128><<<gBig, b, DS128>>>(hf, KT_FULL, W1, CC,
                                   af, KT_FULL, W1 + (size_t)CC * CC, CC,
                                   /*SPLITS=*/2, P, CC, NN);

    // K4 (fused): B = out1 = relu(sum P + b1); out = Wlp @ out1 + bl[:,None]
    tgemm32f<<<gF, b, DS32>>>(Wlp, P, b1, /*brelu=*/1,
                              /*hout=*/nullptr, /*rowbias=*/bl,
                              out, CC, NN);
}

// round 16
// speedup vs baseline: 1.1481x; 1.1481x over previous
#include <cuda_runtime.h>
#include <cuda_bf16.h>
#include <cuda_fp16.h>
#include <cstdint>

#define NN 110
#define CC 4096
#define NPAD 128

#define BM 128
#define BKC 64          // k per chunk
#define PITCHA 72       // 16-bit elems per A smem row (64 + 8 pad)
#define NTH 256

#define PS (NPAD * CC)  // partial buffer stride

// -------------------- scratch (zero-initialized device globals) ------------
__device__ float g_Mn  [NPAD * NPAD];
__device__ float g_Wlp [NPAD * NPAD];
__device__ float g_P   [4 * PS];
// fp16 A operands (rows >= 110 never written -> zero)
__device__ unsigned short g_x16[NPAD * CC];
__device__ unsigned short g_h16[NPAD * CC];
__device__ unsigned short g_a16[NPAD * CC];

// -------------------- helpers ----------------------------------------------
__device__ __forceinline__ uint32_t smem_u32(const void* p) {
    uint32_t a;
    asm("{ .reg .u64 t; cvta.to.shared.u64 t, %1; cvt.u32.u64 %0, t; }"
        : "=r"(a) : "l"(p));
    return a;
}

// bf16 split (small fused kernels)
__device__ __forceinline__ void split2(float x0, float x1, uint32_t& hi, uint32_t& lo) {
    uint32_t h;
    asm("cvt.rn.bf16x2.f32 %0, %1, %2;" : "=r"(h) : "f"(x1), "f"(x0));
    float h0 = __uint_as_float(h << 16);
    float h1 = __uint_as_float(h & 0xFFFF0000u);
    float r0 = x0 - h0;
    float r1 = x1 - h1;
    asm("cvt.rn.bf16x2.f32 %0, %1, %2;" : "=r"(lo) : "f"(r1), "f"(r0));
    hi = h;
}

__device__ __forceinline__ uint32_t cvth2(float x0, float x1) {
    uint32_t h;
    asm("cvt.rn.f16x2.f32 %0, %1, %2;" : "=r"(h) : "f"(x1), "f"(x0));
    return h;
}

#define LDMX4(r, addr)                                                        \
    asm volatile("ldmatrix.sync.aligned.m8n8.x4.shared.b16 {%0,%1,%2,%3}, [%4];" \
        : "=r"((r)[0]), "=r"((r)[1]), "=r"((r)[2]), "=r"((r)[3]) : "r"(addr))

#define LDMX4T(r, addr)                                                       \
    asm volatile("ldmatrix.sync.aligned.m8n8.x4.trans.shared.b16 {%0,%1,%2,%3}, [%4];" \
        : "=r"((r)[0]), "=r"((r)[1]), "=r"((r)[2]), "=r"((r)[3]) : "r"(addr))

#define MMA_BF16(acc, a, b0, b1)                                              \
    asm volatile("mma.sync.aligned.m16n8k16.row.col.f32.bf16.bf16.f32 "       \
        "{%0,%1,%2,%3}, {%4,%5,%6,%7}, {%8,%9}, {%0,%1,%2,%3};"               \
        : "+f"((acc)[0]), "+f"((acc)[1]), "+f"((acc)[2]), "+f"((acc)[3])      \
        : "r"((a)[0]), "r"((a)[1]), "r"((a)[2]), "r"((a)[3]), "r"(b0), "r"(b1))

#define MMA_F16(acc, a, b0, b1)                                               \
    asm volatile("mma.sync.aligned.m16n8k16.row.col.f32.f16.f16.f32 "         \
        "{%0,%1,%2,%3}, {%4,%5,%6,%7}, {%8,%9}, {%0,%1,%2,%3};"               \
        : "+f"((acc)[0]), "+f"((acc)[1]), "+f"((acc)[2]), "+f"((acc)[3])      \
        : "r"((a)[0]), "r"((a)[1]), "r"((a)[2]), "r"((a)[3]), "r"(b0), "r"(b1))

// ---------------------------------------------------------------------------
// Prep: Mn[j][i] = (adj[i][j]!=0)/max(deg_j,1); Wl padded to 128 (fp32).
// ---------------------------------------------------------------------------
__global__ void prep_kernel(const int* __restrict__ adj, const float* __restrict__ Wl) {
    const int j = blockIdx.x;
    const int i = threadIdx.x;
    __shared__ int sdeg[NPAD];
    int a = (i < NN && j < NN) ? (adj[i * NN + j] != 0) : 0;
    sdeg[i] = a;
    __syncthreads();
#pragma unroll
    for (int s = 64; s > 0; s >>= 1) {
        if (i < s) sdeg[i] += sdeg[i + s];
        __syncthreads();
    }
    const int deg = sdeg[0];
    const float inv = (j < NN) ? 1.0f / (float)(deg > 1 ? deg : 1) : 0.0f;
    g_Mn [j * NPAD + i] = a ? inv : 0.0f;
    g_Wlp[j * NPAD + i] = (i < NN && j < NN) ? Wl[j * NN + i] : 0.0f;
}

// ---------------------------------------------------------------------------
// pack16: fp32 [110 x 4096] -> fp16 (row-major, same layout)
// ---------------------------------------------------------------------------
__global__ void pack16(const float* __restrict__ src, unsigned short* __restrict__ dst) {
    int e = (blockIdx.x * blockDim.x + threadIdx.x) * 8;
    if (e >= NN * CC) return;
    float4 a = *(const float4*)(src + e);
    float4 b = *(const float4*)(src + e + 4);
    uint4 o;
    o.x = cvth2(a.x, a.y);
    o.y = cvth2(a.z, a.w);
    o.z = cvth2(b.x, b.y);
    o.w = cvth2(b.z, b.w);
    *(uint4*)(dst + e) = o;
}

// ===========================================================================
// tgemm: big GEMM, single fp16 (A pre-converted fp16 in gmem, B fp32->cvt).
// CTA tile 128 x BNT, 256 thr, 8 warps (4m x 2n), warp tile 32 x (BNT/2).
// Double-buffered smem, one sync per chunk (R14 pipeline). fp32 partials out.
// ===========================================================================
template<int BNT>
__global__ __launch_bounds__(NTH, 1)
void tgemm(const unsigned short* __restrict__ A1, int lda1, int ka1,
           const float* __restrict__ B1, int ldb1,
           const unsigned short* __restrict__ A2, int lda2, int ka2,
           const float* __restrict__ B2, int ldb2,
           int SPLITS,
           float* __restrict__ C, int ldc, int Mreal)
{
    constexpr int NTW = BNT / 16;
    constexpr int PITCHB = BNT + 8;
    constexpr int NBG = NTW / 2;
    constexpr int FB = BNT / 16;
    constexpr uint32_t AH_OFF = 0;
    constexpr uint32_t BH_OFF = BM * PITCHA * 2;             // 18432
    constexpr uint32_t BBYTES = (uint32_t)BKC * PITCHB * 2;  // 17408 @BNT=128
    constexpr uint32_t STAGE  = BH_OFF + BBYTES;             // 35840

    extern __shared__ __align__(16) char dsm[];
    const uint32_t sb = smem_u32(dsm);

    const int tid = threadIdx.x;
    const int wid = tid >> 5;
    const int lid = tid & 31;
    const int ms = wid & 3;
    const int ns = wid >> 2;
    const int n0 = blockIdx.x * BNT;
    const int slice = blockIdx.y;

    const int pair = slice / SPLITS;
    const int q    = slice % SPLITS;
    const unsigned short* A = pair ? A2 : A1;
    const float* B = pair ? B2 : B1;
    const int lda = pair ? lda2 : lda1;
    const int ldb = pair ? ldb2 : ldb1;
    const int kaeff = (pair ? ka2 : ka1) / SPLITS;
    const int kbase = q * kaeff;
    const int T = kaeff / BKC;

    // A loader: 128 rows x 64 halves; 2 threads/row, 32 halves each (4x uint4)
    const int ar2 = tid >> 1;
    const int ac2 = (tid & 1) * 32;
    // B loader: 64 k x BNT n; thread -> (k row, BNT/4 n)
    const int bkq = tid >> 2;
    const int bnq = (tid & 3) * (BNT / 4);

    float acc[2][NTW][4];
#pragma unroll
    for (int a = 0; a < 2; ++a)
#pragma unroll
        for (int b = 0; b < NTW; ++b)
#pragma unroll
            for (int c = 0; c < 4; ++c) acc[a][b][c] = 0.0f;

    const uint32_t aoffH = AH_OFF +
        (((uint32_t)(ms * 32 + (lid & 15)) * PITCHA) + ((lid >> 4) & 1) * 8u) * 2u;
    const uint32_t boff = BH_OFF +
        (((uint32_t)(lid & 15) * PITCHB) + (uint32_t)(ns * (BNT / 2) + (lid >> 4) * 8)) * 2u;

    uint4 fa16[4];
    float4 fbr[FB];

#define LOADG(T_)                                                              \
    do {                                                                       \
        int k0_ = kbase + (T_) * BKC;                                          \
        const unsigned short* pa_ = A + (size_t)ar2 * lda + k0_ + ac2;         \
        _Pragma("unroll")                                                      \
        for (int j = 0; j < 4; ++j)                                            \
            fa16[j] = *(const uint4*)(pa_ + j * 8);                            \
        const float* p_ = B + (size_t)(k0_ + bkq) * ldb + n0 + bnq;            \
        _Pragma("unroll")                                                      \
        for (int j = 0; j < FB; ++j)                                           \
            fbr[j] = *(const float4*)(p_ + j * 4);                             \
    } while (0)

#define STORE_STAGE(bufsel)                                                    \
    do {                                                                       \
        char* st = dsm + (bufsel) * STAGE;                                     \
        {                                                                      \
            uint32_t oA_ = ((uint32_t)ar2 * PITCHA + (uint32_t)ac2) * 2u;      \
            _Pragma("unroll")                                                  \
            for (int j = 0; j < 4; ++j)                                        \
                *(uint4*)(st + AH_OFF + oA_ + j * 16u) = fa16[j];              \
        }                                                                      \
        {                                                                      \
            uint32_t o_ = ((uint32_t)bkq * PITCHB + (uint32_t)bnq) * 2u;       \
            _Pragma("unroll")                                                  \
            for (int j = 0; j < FB; j += 2) {                                  \
                uint4 hv;                                                      \
                hv.x = cvth2(fbr[j].x,     fbr[j].y);                          \
                hv.y = cvth2(fbr[j].z,     fbr[j].w);                          \
                hv.z = cvth2(fbr[j + 1].x, fbr[j + 1].y);                      \
                hv.w = cvth2(fbr[j + 1].z, fbr[j + 1].w);                      \
                *(uint4*)(st + BH_OFF + o_ + j * 8) = hv;                      \
            }                                                                  \
        }                                                                      \
    } while (0)

    LOADG(0);
    STORE_STAGE(0);
    if (T > 1) LOADG(1);
    __syncthreads();

    for (int t = 0; t < T; ++t) {
        const uint32_t base = sb + (uint32_t)(t & 1) * STAGE;
#pragma unroll
        for (int ks = 0; ks < 4; ++ks) {
            const uint32_t kA = (uint32_t)ks * 32u;
            const uint32_t kB = (uint32_t)ks * 16u * PITCHB * 2u;
            uint32_t ah[2][4], bh[NBG][4];
            LDMX4(ah[0], base + aoffH + kA);
            LDMX4(ah[1], base + aoffH + 16u * PITCHA * 2u + kA);
#pragma unroll
            for (int gp = 0; gp < NBG; ++gp)
                LDMX4T(bh[gp], base + boff + gp * 32u + kB);
#pragma unroll
            for (int mt = 0; mt < 2; ++mt)
#pragma unroll
                for (int nt = 0; nt < NTW; ++nt) {
                    const int gp = nt >> 1, ix = (nt & 1) * 2;
                    MMA_F16(acc[mt][nt], ah[mt], bh[gp][ix], bh[gp][ix + 1]);
                }
        }
        if (t + 1 < T) STORE_STAGE((t + 1) & 1);
        if (t + 2 < T) LOADG(t + 2);
        __syncthreads();
    }
#undef LOADG
#undef STORE_STAGE

    const int g  = lid >> 2;
    const int tq = lid & 3;
    float* Pout = C + (size_t)slice * PS;
#pragma unroll
    for (int mt = 0; mt < 2; ++mt) {
#pragma unroll
        for (int nt = 0; nt < NTW; ++nt) {
            int col = n0 + ns * (BNT / 2) + nt * 8 + tq * 2;
#pragma unroll
            for (int half = 0; half < 2; ++half) {
                int m = ms * 32 + mt * 16 + g + half * 8;
                if (m >= Mreal) continue;
                *(float2*)&Pout[(size_t)m * ldc + col] =
                    make_float2(acc[mt][nt][half * 2 + 0], acc[mt][nt][half * 2 + 1]);
            }
        }
    }
}

// ===========================================================================
// tgemm32f: small fused GEMM (bf16 3-term, R12-proven). CTA tile 128x32.
//   B[k][n] = (brelu? relu : id)( sum_{s<4} P_s[k][n] + bcol[n] )
//   computed in the loader; optionally emitted as fp16 to b16out (rows < NN).
// Epilogue: C = A @ B; fp32 out (+rowbias) or fp16 pairs to c16out.
// ===========================================================================
#define BNT32 32
#define PITCHB32 (BNT32 + 8)
#define AH32 0u
#define AL32 ((uint32_t)BM * PITCHA * 2u)            // 18432
#define BH32 (2u * AL32)                             // 36864
#define BB32 ((uint32_t)BKC * PITCHB32 * 2u)         // 5120
#define BL32 (BH32 + BB32)
#define ST32 (BH32 + 2u * BB32)                      // 47104
#define DS32 (2u * ST32)                             // 94208

__global__ __launch_bounds__(NTH, 1)
void tgemm32f(const float* __restrict__ A1,          // 128 x 128, lda = NPAD
              const float* __restrict__ P,           // 4 partial slices
              const float* __restrict__ bcol,        // column bias for B
              int brelu,
              unsigned short* __restrict__ b16out,   // optional: B as fp16
              unsigned short* __restrict__ c16out,   // optional: C as fp16
              const float* __restrict__ rowbias,     // optional per-row bias
              float* __restrict__ C, int ldc, int Mreal)
{
    extern __shared__ __align__(16) char dsm[];
    const uint32_t sb = smem_u32(dsm);

    const int tid = threadIdx.x;
    const int wid = tid >> 5;
    const int lid = tid & 31;
    const int ms = wid & 3;
    const int ns = wid >> 2;
    const int n0 = blockIdx.x * BNT32;

    const int T = NPAD / BKC;   // 2

    const int alrow = tid >> 4;
    const int alc   = (tid & 15) * 4;
    const int bkq = tid >> 2;
    const int bnq = (tid & 3) * 8;

    float acc[2][2][4];
#pragma unroll
    for (int a = 0; a < 2; ++a)
#pragma unroll
        for (int b = 0; b < 2; ++b)
#pragma unroll
            for (int c = 0; c < 4; ++c) acc[a][b][c] = 0.0f;

    const uint32_t aoffH = AH32 +
        (((uint32_t)(ms * 32 + (lid & 15)) * PITCHA) + ((lid >> 4) & 1) * 8u) * 2u;
    const uint32_t boff = BH32 +
        (((uint32_t)(lid & 15) * PITCHB32) + (uint32_t)(ns * 16 + (lid >> 4) * 8)) * 2u;

    float4 fa[8];
    float4 fbr[2];
    const float4 f4z = make_float4(0.f, 0.f, 0.f, 0.f);

#define LOADG(T_)                                                              \
    do {                                                                       \
        int k0_ = (T_) * BKC;                                                  \
        _Pragma("unroll")                                                      \
        for (int p = 0; p < 8; ++p) {                                          \
            int m = p * 16 + alrow;                                            \
            fa[p] = (m < Mreal) ? *(const float4*)(A1 + (size_t)m * NPAD + k0_ + alc) : f4z; \
        }                                                                      \
        int krow = k0_ + bkq;                                                  \
        const float* pp = P + (size_t)krow * CC + n0 + bnq;                    \
        _Pragma("unroll")                                                      \
        for (int j = 0; j < 2; ++j) {                                          \
            float4 p0 = *(const float4*)(pp + j * 4);                          \
            float4 p1 = *(const float4*)(pp + PS + j * 4);                     \
            float4 p2 = *(const float4*)(pp + 2 * PS + j * 4);                 \
            float4 p3 = *(const float4*)(pp + 3 * PS + j * 4);                 \
            float4 bv = *(const float4*)(bcol + n0 + bnq + j * 4);             \
            float4 v;                                                          \
            v.x = (p0.x + p1.x) + (p2.x + p3.x) + bv.x;                        \
            v.y = (p0.y + p1.y) + (p2.y + p3.y) + bv.y;                        \
            v.z = (p0.z + p1.z) + (p2.z + p3.z) + bv.z;                        \
            v.w = (p0.w + p1.w) + (p2.w + p3.w) + bv.w;                        \
            if (brelu) {                                                       \
                v.x = fmaxf(v.x, 0.f); v.y = fmaxf(v.y, 0.f);                  \
                v.z = fmaxf(v.z, 0.f); v.w = fmaxf(v.w, 0.f);                  \
            }                                                                  \
            fbr[j] = v;                                                        \
        }                                                                      \
        if (b16out != nullptr && krow < NN) {                                  \
            uint4 hv;                                                          \
            hv.x = cvth2(fbr[0].x, fbr[0].y);                                  \
            hv.y = cvth2(fbr[0].z, fbr[0].w);                                  \
            hv.z = cvth2(fbr[1].x, fbr[1].y);                                  \
            hv.w = cvth2(fbr[1].z, fbr[1].w);                                  \
            *(uint4*)(b16out + (size_t)krow * CC + n0 + bnq) = hv;             \
        }                                                                      \
    } while (0)

#define STORE_STAGE(bufsel)                                                    \
    do {                                                                       \
        char* st = dsm + (bufsel) * ST32;                                      \
        _Pragma("unroll")                                                      \
        for (int p = 0; p < 8; ++p) {                                          \
            int row = p * 16 + alrow;                                          \
            uint32_t h0, l0, h1, l1;                                           \
            split2(fa[p].x, fa[p].y, h0, l0);                                  \
            split2(fa[p].z, fa[p].w, h1, l1);                                  \
            uint32_t off = ((uint32_t)row * PITCHA + (uint32_t)alc) * 2u;      \
            *(uint2*)(st + AH32 + off) = make_uint2(h0, h1);                   \
            *(uint2*)(st + AL32 + off) = make_uint2(l0, l1);                   \
        }                                                                      \
        {                                                                      \
            uint32_t o_ = ((uint32_t)bkq * PITCHB32 + (uint32_t)bnq) * 2u;     \
            uint4 hv, lv;                                                      \
            split2(fbr[0].x, fbr[0].y, hv.x, lv.x);                            \
            split2(fbr[0].z, fbr[0].w, hv.y, lv.y);                            \
            split2(fbr[1].x, fbr[1].y, hv.z, lv.z);                            \
            split2(fbr[1].z, fbr[1].w, hv.w, lv.w);                            \
            *(uint4*)(st + BH32 + o_) = hv;                                    \
            *(uint4*)(st + BL32 + o_) = lv;                                    \
        }                                                                      \
    } while (0)

    LOADG(0);
    STORE_STAGE(0);
    LOADG(1);
    __syncthreads();

    for (int t = 0; t < T; ++t) {
        const uint32_t base = sb + (uint32_t)(t & 1) * ST32;
#pragma unroll
        for (int ks = 0; ks < 4; ++ks) {
            const uint32_t kA = (uint32_t)ks * 32u;
            const uint32_t kB = (uint32_t)ks * 16u * PITCHB32 * 2u;
            uint32_t ah[2][4], al[2][4], bh[4], bl[4];
            LDMX4(ah[0], base + aoffH + kA);
            LDMX4(ah[1], base + aoffH + 16u * PITCHA * 2u + kA);
            LDMX4(al[0], base + aoffH + (AL32 - AH32) + kA);
            LDMX4(al[1], base + aoffH + (AL32 - AH32) + 16u * PITCHA * 2u + kA);
            LDMX4T(bh, base + boff + kB);
            LDMX4T(bl, base + boff + (BL32 - BH32) + kB);
#pragma unroll
            for (int mt = 0; mt < 2; ++mt)
#pragma unroll
                for (int nt = 0; nt < 2; ++nt) {
                    const int ix = nt * 2;
                    MMA_BF16(acc[mt][nt], ah[mt], bh[ix], bh[ix + 1]);
                    MMA_BF16(acc[mt][nt], ah[mt], bl[ix], bl[ix + 1]);
                    MMA_BF16(acc[mt][nt], al[mt], bh[ix], bh[ix + 1]);
                }
        }
        if (t + 1 < T) STORE_STAGE((t + 1) & 1);
        __syncthreads();
    }
#undef LOADG
#undef STORE_STAGE

    const int g  = lid >> 2;
    const int tq = lid & 3;
#pragma unroll
    for (int mt = 0; mt < 2; ++mt) {
#pragma unroll
        for (int nt = 0; nt < 2; ++nt) {
            int col = n0 + ns * 16 + nt * 8 + tq * 2;
#pragma unroll
            for (int half = 0; half < 2; ++half) {
                int m = ms * 32 + mt * 16 + g + half * 8;
                if (m >= Mreal) continue;
                float rb = (rowbias != nullptr) ? rowbias[m] : 0.0f;
                float vx = acc[mt][nt][half * 2 + 0] + rb;
                float vy = acc[mt][nt][half * 2 + 1] + rb;
                if (c16out != nullptr) {
                    *(uint32_t*)(c16out + (size_t)m * ldc + col) = cvth2(vx, vy);
                } else {
                    *(float2*)&C[(size_t)m * ldc + col] = make_float2(vx, vy);
                }
            }
        }
    }
}

// ---------------------------------------------------------------------------
extern "C" void kernel_launch(void* const* d_in, const int* in_sizes, int n_in,
                              void* d_out, int out_size)
{
    const float* x   = (const float*)d_in[0];
    const int*   adj = (const int*)  d_in[1];
    const float* W2  = (const float*)d_in[2];
    const float* b2  = (const float*)d_in[3];
    const float* W1  = (const float*)d_in[4];
    const float* b1  = (const float*)d_in[5];
    const float* Wl  = (const float*)d_in[6];
    const float* bl  = (const float*)d_in[7];
    float* out = (float*)d_out;

    float *Mn, *Wlp, *P;
    unsigned short *x16, *h16, *a16;
    cudaGetSymbolAddress((void**)&Mn,  g_Mn);
    cudaGetSymbolAddress((void**)&Wlp, g_Wlp);
    cudaGetSymbolAddress((void**)&P,   g_P);
    cudaGetSymbolAddress((void**)&x16, g_x16);
    cudaGetSymbolAddress((void**)&h16, g_h16);
    cudaGetSymbolAddress((void**)&a16, g_a16);

    // stage: A fp16 (18432) + B fp16 (17408), double-buffered
    const int DS128 = 2 * (BM * PITCHA * 2 + BKC * (128 + 8) * 2);   // 71680
    cudaFuncSetAttribute(tgemm<128>, cudaFuncAttributeMaxDynamicSharedMemorySize, DS128);
    cudaFuncSetAttribute(tgemm32f, cudaFuncAttributeMaxDynamicSharedMemorySize, DS32);

    dim3 b(NTH);
    dim3 gBig(CC / 128, 4);    // 32 x 4 slices = 128 CTAs
    dim3 gF  (CC / BNT32);     // 128 CTAs

    prep_kernel<<<NPAD, NPAD>>>(adj, Wl);
    pack16<<<(NN * CC / 8 + 255) / 256, 256>>>(x, x16);

    // K1: P_s = x16 @ W2 over 4 k-slices of 1024 (single fp16)
    tgemm<128><<<gBig, b, DS128>>>(x16, CC, CC, W2, CC,
                                   nullptr, 0, 0, nullptr, 0,
                                   /*SPLITS=*/4, P, CC, NN);

    // K2 (fused): B = h = sum P + b2 (emitted as h16);
    //             aggr = Mn @ h (emitted as a16)
    tgemm32f<<<gF, b, DS32>>>(Mn, P, b2, /*brelu=*/0,
                              /*b16out=*/h16, /*c16out=*/a16,
                              /*rowbias=*/nullptr,
                              nullptr, CC, NN);

    // K3: P_s = (h16 @ W1_top | a16 @ W1_bot), each pair split in 2
    tgemm<128><<<gBig, b, DS128>>>(h16, CC, CC, W1, CC,
                                   a16, CC, CC, W1 + (size_t)CC * CC, CC,
                                   /*SPLITS=*/2, P, CC, NN);

    // K4 (fused): B = out1 = relu(sum P + b1); out = Wlp @ out1 + bl[:,None]
    tgemm32f<<<gF, b, DS32>>>(Wlp, P, b1, /*brelu=*/1,
                              /*b16out=*/nullptr, /*c16out=*/nullptr,
                              /*rowbias=*/bl,
                              out, CC, NN);
}

// round 17
// speedup vs baseline: 1.2357x; 1.0764x over previous
#include <cuda_runtime.h>
#include <cuda_bf16.h>
#include <cuda_fp16.h>
#include <cstdint>

#define NN 110
#define CC 4096
#define NPAD 128

#define BM 128
#define BKC 64          // k per chunk
#define PITCHA 72       // 16-bit elems per A smem row (64 + 8 pad)
#define NTH 256

#define PS (NPAD * CC)  // partial buffer stride

// -------------------- scratch (zero-initialized device globals) ------------
__device__ float g_Mn  [NPAD * NPAD];
__device__ float g_Wlp [NPAD * NPAD];
__device__ float g_P   [4 * PS];
// fp16 A operands (rows >= 110 never written -> zero)
__device__ unsigned short g_x16[NPAD * CC];
__device__ unsigned short g_h16[NPAD * CC];
__device__ unsigned short g_a16[NPAD * CC];

// -------------------- helpers ----------------------------------------------
__device__ __forceinline__ uint32_t smem_u32(const void* p) {
    uint32_t a;
    asm("{ .reg .u64 t; cvta.to.shared.u64 t, %1; cvt.u32.u64 %0, t; }"
        : "=r"(a) : "l"(p));
    return a;
}

// bf16 split (small fused kernels)
__device__ __forceinline__ void split2(float x0, float x1, uint32_t& hi, uint32_t& lo) {
    uint32_t h;
    asm("cvt.rn.bf16x2.f32 %0, %1, %2;" : "=r"(h) : "f"(x1), "f"(x0));
    float h0 = __uint_as_float(h << 16);
    float h1 = __uint_as_float(h & 0xFFFF0000u);
    float r0 = x0 - h0;
    float r1 = x1 - h1;
    asm("cvt.rn.bf16x2.f32 %0, %1, %2;" : "=r"(lo) : "f"(r1), "f"(r0));
    hi = h;
}

__device__ __forceinline__ uint32_t cvth2(float x0, float x1) {
    uint32_t h;
    asm("cvt.rn.f16x2.f32 %0, %1, %2;" : "=r"(h) : "f"(x1), "f"(x0));
    return h;
}

#define LDMX4(r, addr)                                                        \
    asm volatile("ldmatrix.sync.aligned.m8n8.x4.shared.b16 {%0,%1,%2,%3}, [%4];" \
        : "=r"((r)[0]), "=r"((r)[1]), "=r"((r)[2]), "=r"((r)[3]) : "r"(addr))

#define LDMX4T(r, addr)                                                       \
    asm volatile("ldmatrix.sync.aligned.m8n8.x4.trans.shared.b16 {%0,%1,%2,%3}, [%4];" \
        : "=r"((r)[0]), "=r"((r)[1]), "=r"((r)[2]), "=r"((r)[3]) : "r"(addr))

#define MMA_BF16(acc, a, b0, b1)                                              \
    asm volatile("mma.sync.aligned.m16n8k16.row.col.f32.bf16.bf16.f32 "       \
        "{%0,%1,%2,%3}, {%4,%5,%6,%7}, {%8,%9}, {%0,%1,%2,%3};"               \
        : "+f"((acc)[0]), "+f"((acc)[1]), "+f"((acc)[2]), "+f"((acc)[3])      \
        : "r"((a)[0]), "r"((a)[1]), "r"((a)[2]), "r"((a)[3]), "r"(b0), "r"(b1))

#define MMA_F16(acc, a, b0, b1)                                               \
    asm volatile("mma.sync.aligned.m16n8k16.row.col.f32.f16.f16.f32 "         \
        "{%0,%1,%2,%3}, {%4,%5,%6,%7}, {%8,%9}, {%0,%1,%2,%3};"               \
        : "+f"((acc)[0]), "+f"((acc)[1]), "+f"((acc)[2]), "+f"((acc)[3])      \
        : "r"((a)[0]), "r"((a)[1]), "r"((a)[2]), "r"((a)[3]), "r"(b0), "r"(b1))

// ---------------------------------------------------------------------------
// Prep: Mn[j][i] = (adj[i][j]!=0)/max(deg_j,1); Wl padded to 128 (fp32).
// ---------------------------------------------------------------------------
__global__ void prep_kernel(const int* __restrict__ adj, const float* __restrict__ Wl) {
    const int j = blockIdx.x;
    const int i = threadIdx.x;
    __shared__ int sdeg[NPAD];
    int a = (i < NN && j < NN) ? (adj[i * NN + j] != 0) : 0;
    sdeg[i] = a;
    __syncthreads();
#pragma unroll
    for (int s = 64; s > 0; s >>= 1) {
        if (i < s) sdeg[i] += sdeg[i + s];
        __syncthreads();
    }
    const int deg = sdeg[0];
    const float inv = (j < NN) ? 1.0f / (float)(deg > 1 ? deg : 1) : 0.0f;
    g_Mn [j * NPAD + i] = a ? inv : 0.0f;
    g_Wlp[j * NPAD + i] = (i < NN && j < NN) ? Wl[j * NN + i] : 0.0f;
}

// ---------------------------------------------------------------------------
// pack16: fp32 [110 x 4096] -> fp16 (row-major, same layout)
// ---------------------------------------------------------------------------
__global__ void pack16(const float* __restrict__ src, unsigned short* __restrict__ dst) {
    int e = (blockIdx.x * blockDim.x + threadIdx.x) * 8;
    if (e >= NN * CC) return;
    float4 a = *(const float4*)(src + e);
    float4 b = *(const float4*)(src + e + 4);
    uint4 o;
    o.x = cvth2(a.x, a.y);
    o.y = cvth2(a.z, a.w);
    o.z = cvth2(b.x, b.y);
    o.w = cvth2(b.z, b.w);
    *(uint4*)(dst + e) = o;
}

// ===========================================================================
// tgemm: big GEMM, single fp16 (A pre-converted fp16 in gmem, B fp32->cvt).
// CTA tile 128 x BNT, 256 thr, 8 warps (4m x 2n), warp tile 32 x (BNT/2).
// Double-buffered smem, one sync per chunk. A loader: 8 threads/row (fully
// coalesced 128B rows). fp32 partials out.
// ===========================================================================
template<int BNT>
__global__ __launch_bounds__(NTH, 1)
void tgemm(const unsigned short* __restrict__ A1, int lda1, int ka1,
           const float* __restrict__ B1, int ldb1,
           const unsigned short* __restrict__ A2, int lda2, int ka2,
           const float* __restrict__ B2, int ldb2,
           int SPLITS,
           float* __restrict__ C, int ldc, int Mreal)
{
    constexpr int NTW = BNT / 16;
    constexpr int PITCHB = BNT + 8;
    constexpr int NBG = NTW / 2;
    constexpr int FB = BNT / 16;
    constexpr uint32_t AH_OFF = 0;
    constexpr uint32_t BH_OFF = BM * PITCHA * 2;             // 18432
    constexpr uint32_t BBYTES = (uint32_t)BKC * PITCHB * 2;  // 17408 @BNT=128
    constexpr uint32_t STAGE  = BH_OFF + BBYTES;             // 35840

    extern __shared__ __align__(16) char dsm[];
    const uint32_t sb = smem_u32(dsm);

    const int tid = threadIdx.x;
    const int wid = tid >> 5;
    const int lid = tid & 31;
    const int ms = wid & 3;
    const int ns = wid >> 2;
    const int n0 = blockIdx.x * BNT;
    const int slice = blockIdx.y;

    const int pair = slice / SPLITS;
    const int q    = slice % SPLITS;
    const unsigned short* A = pair ? A2 : A1;
    const float* B = pair ? B2 : B1;
    const int lda = pair ? lda2 : lda1;
    const int ldb = pair ? ldb2 : ldb1;
    const int kaeff = (pair ? ka2 : ka1) / SPLITS;
    const int kbase = q * kaeff;
    const int T = kaeff / BKC;

    // A loader: 8 threads/row, 1 uint4 each, 4 passes of 32 rows (coalesced)
    const int arow = tid >> 3;           // 0..31
    const int acol = (tid & 7) * 8;      // halves
    // B loader: 64 k x BNT n; thread -> (k row, BNT/4 n)
    const int bkq = tid >> 2;
    const int bnq = (tid & 3) * (BNT / 4);

    float acc[2][NTW][4];
#pragma unroll
    for (int a = 0; a < 2; ++a)
#pragma unroll
        for (int b = 0; b < NTW; ++b)
#pragma unroll
            for (int c = 0; c < 4; ++c) acc[a][b][c] = 0.0f;

    const uint32_t aoffH = AH_OFF +
        (((uint32_t)(ms * 32 + (lid & 15)) * PITCHA) + ((lid >> 4) & 1) * 8u) * 2u;
    const uint32_t boff = BH_OFF +
        (((uint32_t)(lid & 15) * PITCHB) + (uint32_t)(ns * (BNT / 2) + (lid >> 4) * 8)) * 2u;

    uint4 fa16[4];
    float4 fbr[FB];

#define LOADG(T_)                                                              \
    do {                                                                       \
        int k0_ = kbase + (T_) * BKC;                                          \
        _Pragma("unroll")                                                      \
        for (int p = 0; p < 4; ++p) {                                          \
            int row = p * 32 + arow;                                           \
            fa16[p] = *(const uint4*)(A + (size_t)row * lda + k0_ + acol);     \
        }                                                                      \
        const float* p_ = B + (size_t)(k0_ + bkq) * ldb + n0 + bnq;            \
        _Pragma("unroll")                                                      \
        for (int j = 0; j < FB; ++j)                                           \
            fbr[j] = *(const float4*)(p_ + j * 4);                             \
    } while (0)

#define STORE_STAGE(bufsel)                                                    \
    do {                                                                       \
        char* st = dsm + (bufsel) * STAGE;                                     \
        _Pragma("unroll")                                                      \
        for (int p = 0; p < 4; ++p) {                                          \
            int row = p * 32 + arow;                                           \
            uint32_t oA_ = ((uint32_t)row * PITCHA + (uint32_t)acol) * 2u;     \
            *(uint4*)(st + AH_OFF + oA_) = fa16[p];                            \
        }                                                                      \
        {                                                                      \
            uint32_t o_ = ((uint32_t)bkq * PITCHB + (uint32_t)bnq) * 2u;       \
            _Pragma("unroll")                                                  \
            for (int j = 0; j < FB; j += 2) {                                  \
                uint4 hv;                                                      \
                hv.x = cvth2(fbr[j].x,     fbr[j].y);                          \
                hv.y = cvth2(fbr[j].z,     fbr[j].w);                          \
                hv.z = cvth2(fbr[j + 1].x, fbr[j + 1].y);                      \
                hv.w = cvth2(fbr[j + 1].z, fbr[j + 1].w);                      \
                *(uint4*)(st + BH_OFF + o_ + j * 8) = hv;                      \
            }                                                                  \
        }                                                                      \
    } while (0)

    LOADG(0);
    STORE_STAGE(0);
    if (T > 1) LOADG(1);
    __syncthreads();

    for (int t = 0; t < T; ++t) {
        const uint32_t base = sb + (uint32_t)(t & 1) * STAGE;
#pragma unroll
        for (int ks = 0; ks < 4; ++ks) {
            const uint32_t kA = (uint32_t)ks * 32u;
            const uint32_t kB = (uint32_t)ks * 16u * PITCHB * 2u;
            uint32_t ah[2][4], bh[NBG][4];
            LDMX4(ah[0], base + aoffH + kA);
            LDMX4(ah[1], base + aoffH + 16u * PITCHA * 2u + kA);
#pragma unroll
            for (int gp = 0; gp < NBG; ++gp)
                LDMX4T(bh[gp], base + boff + gp * 32u + kB);
#pragma unroll
            for (int mt = 0; mt < 2; ++mt)
#pragma unroll
                for (int nt = 0; nt < NTW; ++nt) {
                    const int gp = nt >> 1, ix = (nt & 1) * 2;
                    MMA_F16(acc[mt][nt], ah[mt], bh[gp][ix], bh[gp][ix + 1]);
                }
        }
        if (t + 1 < T) STORE_STAGE((t + 1) & 1);
        if (t + 2 < T) LOADG(t + 2);
        __syncthreads();
    }
#undef LOADG
#undef STORE_STAGE

    const int g  = lid >> 2;
    const int tq = lid & 3;
    float* Pout = C + (size_t)slice * PS;
#pragma unroll
    for (int mt = 0; mt < 2; ++mt) {
#pragma unroll
        for (int nt = 0; nt < NTW; ++nt) {
            int col = n0 + ns * (BNT / 2) + nt * 8 + tq * 2;
#pragma unroll
            for (int half = 0; half < 2; ++half) {
                int m = ms * 32 + mt * 16 + g + half * 8;
                if (m >= Mreal) continue;
                *(float2*)&Pout[(size_t)m * ldc + col] =
                    make_float2(acc[mt][nt][half * 2 + 0], acc[mt][nt][half * 2 + 1]);
            }
        }
    }
}

// ===========================================================================
// tgemm32f: small fused GEMM (bf16 3-term, R12-proven). CTA tile 128x32.
//   B[k][n] = (brelu? relu : id)( sum_{s<4} P_s[k][n] + bcol[n] )
//   computed in the loader; optionally emitted as fp16 to b16out (rows < NN).
// Epilogue: C = A @ B; fp32 out (+rowbias) or fp16 pairs to c16out.
// ===========================================================================
#define BNT32 32
#define PITCHB32 (BNT32 + 8)
#define AH32 0u
#define AL32 ((uint32_t)BM * PITCHA * 2u)            // 18432
#define BH32 (2u * AL32)                             // 36864
#define BB32 ((uint32_t)BKC * PITCHB32 * 2u)         // 5120
#define BL32 (BH32 + BB32)
#define ST32 (BH32 + 2u * BB32)                      // 47104
#define DS32 (2u * ST32)                             // 94208

__global__ __launch_bounds__(NTH, 1)
void tgemm32f(const float* __restrict__ A1,          // 128 x 128, lda = NPAD
              const float* __restrict__ P,           // 4 partial slices
              const float* __restrict__ bcol,        // column bias for B
              int brelu,
              unsigned short* __restrict__ b16out,   // optional: B as fp16
              unsigned short* __restrict__ c16out,   // optional: C as fp16
              const float* __restrict__ rowbias,     // optional per-row bias
              float* __restrict__ C, int ldc, int Mreal)
{
    extern __shared__ __align__(16) char dsm[];
    const uint32_t sb = smem_u32(dsm);

    const int tid = threadIdx.x;
    const int wid = tid >> 5;
    const int lid = tid & 31;
    const int ms = wid & 3;
    const int ns = wid >> 2;
    const int n0 = blockIdx.x * BNT32;

    const int T = NPAD / BKC;   // 2

    const int alrow = tid >> 4;
    const int alc   = (tid & 15) * 4;
    const int bkq = tid >> 2;
    const int bnq = (tid & 3) * 8;

    float acc[2][2][4];
#pragma unroll
    for (int a = 0; a < 2; ++a)
#pragma unroll
        for (int b = 0; b < 2; ++b)
#pragma unroll
            for (int c = 0; c < 4; ++c) acc[a][b][c] = 0.0f;

    const uint32_t aoffH = AH32 +
        (((uint32_t)(ms * 32 + (lid & 15)) * PITCHA) + ((lid >> 4) & 1) * 8u) * 2u;
    const uint32_t boff = BH32 +
        (((uint32_t)(lid & 15) * PITCHB32) + (uint32_t)(ns * 16 + (lid >> 4) * 8)) * 2u;

    float4 fa[8];
    float4 fbr[2];
    const float4 f4z = make_float4(0.f, 0.f, 0.f, 0.f);

#define LOADG(T_)                                                              \
    do {                                                                       \
        int k0_ = (T_) * BKC;                                                  \
        _Pragma("unroll")                                                      \
        for (int p = 0; p < 8; ++p) {                                          \
            int m = p * 16 + alrow;                                            \
            fa[p] = (m < Mreal) ? *(const float4*)(A1 + (size_t)m * NPAD + k0_ + alc) : f4z; \
        }                                                                      \
        int krow = k0_ + bkq;                                                  \
        const float* pp = P + (size_t)krow * CC + n0 + bnq;                    \
        _Pragma("unroll")                                                      \
        for (int j = 0; j < 2; ++j) {                                          \
            float4 p0 = *(const float4*)(pp + j * 4);                          \
            float4 p1 = *(const float4*)(pp + PS + j * 4);                     \
            float4 p2 = *(const float4*)(pp + 2 * PS + j * 4);                 \
            float4 p3 = *(const float4*)(pp + 3 * PS + j * 4);                 \
            float4 bv = *(const float4*)(bcol + n0 + bnq + j * 4);             \
            float4 v;                                                          \
            v.x = (p0.x + p1.x) + (p2.x + p3.x) + bv.x;                        \
            v.y = (p0.y + p1.y) + (p2.y + p3.y) + bv.y;                        \
            v.z = (p0.z + p1.z) + (p2.z + p3.z) + bv.z;                        \
            v.w = (p0.w + p1.w) + (p2.w + p3.w) + bv.w;                        \
            if (brelu) {                                                       \
                v.x = fmaxf(v.x, 0.f); v.y = fmaxf(v.y, 0.f);                  \
                v.z = fmaxf(v.z, 0.f); v.w = fmaxf(v.w, 0.f);                  \
            }                                                                  \
            fbr[j] = v;                                                        \
        }                                                                      \
        if (b16out != nullptr && krow < NN) {                                  \
            uint4 hv;                                                          \
            hv.x = cvth2(fbr[0].x, fbr[0].y);                                  \
            hv.y = cvth2(fbr[0].z, fbr[0].w);                                  \
            hv.z = cvth2(fbr[1].x, fbr[1].y);                                  \
            hv.w = cvth2(fbr[1].z, fbr[1].w);                                  \
            *(uint4*)(b16out + (size_t)krow * CC + n0 + bnq) = hv;             \
        }                                                                      \
    } while (0)

#define STORE_STAGE(bufsel)                                                    \
    do {                                                                       \
        char* st = dsm + (bufsel) * ST32;                                      \
        _Pragma("unroll")                                                      \
        for (int p = 0; p < 8; ++p) {                                          \
            int row = p * 16 + alrow;                                          \
            uint32_t h0, l0, h1, l1;                                           \
            split2(fa[p].x, fa[p].y, h0, l0);                                  \
            split2(fa[p].z, fa[p].w, h1, l1);                                  \
            uint32_t off = ((uint32_t)row * PITCHA + (uint32_t)alc) * 2u;      \
            *(uint2*)(st + AH32 + off) = make_uint2(h0, h1);                   \
            *(uint2*)(st + AL32 + off) = make_uint2(l0, l1);                   \
        }                                                                      \
        {                                                                      \
            uint32_t o_ = ((uint32_t)bkq * PITCHB32 + (uint32_t)bnq) * 2u;     \
            uint4 hv, lv;                                                      \
            split2(fbr[0].x, fbr[0].y, hv.x, lv.x);                            \
            split2(fbr[0].z, fbr[0].w, hv.y, lv.y);                            \
            split2(fbr[1].x, fbr[1].y, hv.z, lv.z);                            \
            split2(fbr[1].z, fbr[1].w, hv.w, lv.w);                            \
            *(uint4*)(st + BH32 + o_) = hv;                                    \
            *(uint4*)(st + BL32 + o_) = lv;                                    \
        }                                                                      \
    } while (0)

    LOADG(0);
    STORE_STAGE(0);
    LOADG(1);
    __syncthreads();

    for (int t = 0; t < T; ++t) {
        const uint32_t base = sb + (uint32_t)(t & 1) * ST32;
#pragma unroll
        for (int ks = 0; ks < 4; ++ks) {
            const uint32_t kA = (uint32_t)ks * 32u;
            const uint32_t kB = (uint32_t)ks * 16u * PITCHB32 * 2u;
            uint32_t ah[2][4], al[2][4], bh[4], bl[4];
            LDMX4(ah[0], base + aoffH + kA);
            LDMX4(ah[1], base + aoffH + 16u * PITCHA * 2u + kA);
            LDMX4(al[0], base + aoffH + (AL32 - AH32) + kA);
            LDMX4(al[1], base + aoffH + (AL32 - AH32) + 16u * PITCHA * 2u + kA);
            LDMX4T(bh, base + boff + kB);
            LDMX4T(bl, base + boff + (BL32 - BH32) + kB);
#pragma unroll
            for (int mt = 0; mt < 2; ++mt)
#pragma unroll
                for (int nt = 0; nt < 2; ++nt) {
                    const int ix = nt * 2;
                    MMA_BF16(acc[mt][nt], ah[mt], bh[ix], bh[ix + 1]);
                    MMA_BF16(acc[mt][nt], ah[mt], bl[ix], bl[ix + 1]);
                    MMA_BF16(acc[mt][nt], al[mt], bh[ix], bh[ix + 1]);
                }
        }
        if (t + 1 < T) STORE_STAGE((t + 1) & 1);
        __syncthreads();
    }
#undef LOADG
#undef STORE_STAGE

    const int g  = lid >> 2;
    const int tq = lid & 3;
#pragma unroll
    for (int mt = 0; mt < 2; ++mt) {
#pragma unroll
        for (int nt = 0; nt < 2; ++nt) {
            int col = n0 + ns * 16 + nt * 8 + tq * 2;
#pragma unroll
            for (int half = 0; half < 2; ++half) {
                int m = ms * 32 + mt * 16 + g + half * 8;
                if (m >= Mreal) continue;
                float rb = (rowbias != nullptr) ? rowbias[m] : 0.0f;
                float vx = acc[mt][nt][half * 2 + 0] + rb;
                float vy = acc[mt][nt][half * 2 + 1] + rb;
                if (c16out != nullptr) {
                    *(uint32_t*)(c16out + (size_t)m * ldc + col) = cvth2(vx, vy);
                } else {
                    *(float2*)&C[(size_t)m * ldc + col] = make_float2(vx, vy);
                }
            }
        }
    }
}

// ---------------------------------------------------------------------------
extern "C" void kernel_launch(void* const* d_in, const int* in_sizes, int n_in,
                              void* d_out, int out_size)
{
    const float* x   = (const float*)d_in[0];
    const int*   adj = (const int*)  d_in[1];
    const float* W2  = (const float*)d_in[2];
    const float* b2  = (const float*)d_in[3];
    const float* W1  = (const float*)d_in[4];
    const float* b1  = (const float*)d_in[5];
    const float* Wl  = (const float*)d_in[6];
    const float* bl  = (const float*)d_in[7];
    float* out = (float*)d_out;

    float *Mn, *Wlp, *P;
    unsigned short *x16, *h16, *a16;
    cudaGetSymbolAddress((void**)&Mn,  g_Mn);
    cudaGetSymbolAddress((void**)&Wlp, g_Wlp);
    cudaGetSymbolAddress((void**)&P,   g_P);
    cudaGetSymbolAddress((void**)&x16, g_x16);
    cudaGetSymbolAddress((void**)&h16, g_h16);
    cudaGetSymbolAddress((void**)&a16, g_a16);

    // stage: A fp16 (18432) + B fp16 (17408), double-buffered
    const int DS128 = 2 * (BM * PITCHA * 2 + BKC * (128 + 8) * 2);   // 71680
    cudaFuncSetAttribute(tgemm<128>, cudaFuncAttributeMaxDynamicSharedMemorySize, DS128);
    cudaFuncSetAttribute(tgemm32f, cudaFuncAttributeMaxDynamicSharedMemorySize, DS32);

    dim3 b(NTH);
    dim3 gBig(CC / 128, 4);    // 32 x 4 slices = 128 CTAs
    dim3 gF  (CC / BNT32);     // 128 CTAs

    prep_kernel<<<NPAD, NPAD>>>(adj, Wl);
    pack16<<<(NN * CC / 8 + 255) / 256, 256>>>(x, x16);

    // K1: P_s = x16 @ W2 over 4 k-slices of 1024 (single fp16)
    tgemm<128><<<gBig, b, DS128>>>(x16, CC, CC, W2, CC,
                                   nullptr, 0, 0, nullptr, 0,
                                   /*SPLITS=*/4, P, CC, NN);

    // K2 (fused): B = h = sum P + b2 (emitted as h16);
    //             aggr = Mn @ h (emitted as a16)
    tgemm32f<<<gF, b, DS32>>>(Mn, P, b2, /*brelu=*/0,
                              /*b16out=*/h16, /*c16out=*/a16,
                              /*rowbias=*/nullptr,
                              nullptr, CC, NN);

    // K3: P_s = (h16 @ W1_top | a16 @ W1_bot), each pair split in 2
    tgemm<128><<<gBig, b, DS128>>>(h16, CC, CC, W1, CC,
                                   a16, CC, CC, W1 + (size_t)CC * CC, CC,
                                   /*SPLITS=*/2, P, CC, NN);

    // K4 (fused): B = out1 = relu(sum P + b1); out = Wlp @ out1 + bl[:,None]
    tgemm32f<<<gF, b, DS32>>>(Wlp, P, b1, /*brelu=*/1,
                              /*b16out=*/nullptr, /*c16out=*/nullptr,
                              /*rowbias=*/bl,
                              out, CC, NN);
}